// round 3
// baseline (speedup 1.0000x reference)
#include <cuda_runtime.h>
#include <math.h>

#define BGRAPHS 512
#define NP      512
#define DIM     256
#define TOPK    32
#define NTHREADS 256
#define NWARPS   8

__global__ __launch_bounds__(NTHREADS, 4)
void pool_topk_kernel(const float* __restrict__ feat,
                      const float* __restrict__ w,
                      const float* __restrict__ b,
                      float* __restrict__ out)
{
    __shared__ float gate_s[NP];
    __shared__ int   topk_s[TOPK];

    const int tid  = threadIdx.x;
    const int warp = tid >> 5;
    const int lane = tid & 31;
    const int g    = blockIdx.x;

    // Each lane owns 8 contiguous w entries (same for every node) — registers.
    const float4 w0 = *reinterpret_cast<const float4*>(w + lane * 8);
    const float4 w1 = *reinterpret_cast<const float4*>(w + lane * 8 + 4);
    const float  bias = b[0];

    const float* fbase = feat + (size_t)g * NP * DIM;

    // -------- Phase A: gates. warp-per-node, 64 nodes per warp. --------
    #pragma unroll 4
    for (int n = warp; n < NP; n += NWARPS) {
        const float* row = fbase + (size_t)n * DIM + lane * 8;
        float4 f0 = *reinterpret_cast<const float4*>(row);
        float4 f1 = *reinterpret_cast<const float4*>(row + 4);
        float p = f0.x * w0.x + f0.y * w0.y + f0.z * w0.z + f0.w * w0.w
                + f1.x * w1.x + f1.y * w1.y + f1.z * w1.z + f1.w * w1.w;
        #pragma unroll
        for (int o = 16; o; o >>= 1)
            p += __shfl_xor_sync(0xffffffffu, p, o);
        if (lane == 0) gate_s[n] = p + bias;
    }
    __syncthreads();

    // -------- Phase B: warp 0 selects top-32 (desc, ties -> smaller idx) ----
    if (warp == 0) {
        float v[16];
        #pragma unroll
        for (int j = 0; j < 16; j++) v[j] = gate_s[lane + 32 * j];

        for (int k = 0; k < TOPK; k++) {
            // local argmax over this lane's 16 values (first hit = smallest idx)
            float best = v[0]; int bj = 0;
            #pragma unroll
            for (int j = 1; j < 16; j++)
                if (v[j] > best) { best = v[j]; bj = j; }
            float bv = best;
            int   bi = lane + 32 * bj;
            // warp argmax with tie-break on smaller global index
            #pragma unroll
            for (int o = 16; o; o >>= 1) {
                float ov = __shfl_xor_sync(0xffffffffu, bv, o);
                int   oi = __shfl_xor_sync(0xffffffffu, bi, o);
                if (ov > bv || (ov == bv && oi < bi)) { bv = ov; bi = oi; }
            }
            if (lane == 0) topk_s[k] = bi;
            // retire the winner from its owning lane's registers
            if ((bi & 31) == lane) v[bi >> 5] = -INFINITY;
        }
    }
    __syncthreads();

    // -------- Phase C: gather selected rows to output --------
    #pragma unroll
    for (int k = warp; k < TOPK; k += NWARPS) {
        const int nid = topk_s[k];
        const float* src = fbase + (size_t)nid * DIM + lane * 8;
        float*       dst = out + ((size_t)g * TOPK + k) * DIM + lane * 8;
        float4 a0 = *reinterpret_cast<const float4*>(src);
        float4 a1 = *reinterpret_cast<const float4*>(src + 4);
        *reinterpret_cast<float4*>(dst)     = a0;
        *reinterpret_cast<float4*>(dst + 4) = a1;
    }
}

extern "C" void kernel_launch(void* const* d_in, const int* in_sizes, int n_in,
                              void* d_out, int out_size)
{
    const float* feat = (const float*)d_in[0];
    const float* w    = (const float*)d_in[1];
    const float* b    = (const float*)d_in[2];
    // d_in[3] = segment_ids: fixed 512 nodes/graph layout, implicit in indexing.
    float* out = (float*)d_out;

    pool_topk_kernel<<<BGRAPHS, NTHREADS>>>(feat, w, b, out);
}